// round 1
// baseline (speedup 1.0000x reference)
#include <cuda_runtime.h>

// PosMLP: per-query generated tiny MLP over a 48x48 grid.
// Fixed problem constants (from reference setup_inputs):
constexpr int C_DIM   = 256;       // query channels
constexpr int HD      = 16;        // hidden dim
constexpr int NW      = 4*HD + 1;  // 65 generated weights per query
constexpr int GH      = 48;        // grid H
constexpr int GW      = 48;        // grid W
constexpr int THREADS = 192;       // 6 warps
constexpr int NQUAD   = GH * (GW/4);  // 576 quad-outputs per query

__global__ __launch_bounds__(THREADS)
void posmlp_kernel(const float* __restrict__ queries,
                   const float* __restrict__ pos,
                   const float* __restrict__ w_gen,
                   const float* __restrict__ b_gen,
                   float* __restrict__ out)
{
    __shared__ __align__(16) float s_q[C_DIM];
    __shared__ float s_w[NW];
    __shared__ __align__(16) float s_ty[HD][GH];  // ty[k][h] = rel_y[h]*w1y[k] + b1[k]
    __shared__ __align__(16) float s_tx[HD][GW];  // tx[k][w] = rel_x[w]*w1x[k]

    const int bq   = blockIdx.x;
    const int tid  = threadIdx.x;
    const int warp = tid >> 5;
    const int lane = tid & 31;

    // ---- Phase 0: stage query row in smem (coalesced) ----
    const float* qrow = queries + (size_t)bq * C_DIM;
    #pragma unroll
    for (int c = tid; c < C_DIM; c += THREADS) s_q[c] = qrow[c];
    __syncthreads();

    // ---- Phase 1: weights[n] = dot(q, w_gen[n]) + b_gen[n], warp-cooperative ----
    for (int n = warp; n < NW; n += (THREADS/32)) {
        const float* wrow = w_gen + n * C_DIM;
        float s = 0.f;
        #pragma unroll
        for (int j = 0; j < C_DIM/32; ++j) {
            int c = lane + 32*j;
            s = fmaf(s_q[c], wrow[c], s);   // wrow coalesced, s_q conflict-free
        }
        #pragma unroll
        for (int off = 16; off; off >>= 1)
            s += __shfl_xor_sync(0xffffffffu, s, off);
        if (lane == 0) s_w[n] = s + b_gen[n];
    }
    __syncthreads();

    // ---- Phase 2: separable precompute ty[k][h], tx[k][w] ----
    const float cx = pos[bq*4 + 0];
    const float cy = pos[bq*4 + 1];
    const float bw = pos[bq*4 + 2];
    const float bh = pos[bq*4 + 3];
    const float inv_bh = 1.0f / bh;
    const float inv_bw = 1.0f / bw;

    for (int i = tid; i < HD*GH; i += THREADS) {
        int k = i / GH, h = i % GH;
        float gy    = ((float)h + 0.5f) * (1.0f / (float)GH);
        float rel_y = (gy - cy) * inv_bh;
        s_ty[k][h] = fmaf(rel_y, s_w[2*k], s_w[2*HD + k]);   // w1y[k], b1[k]
    }
    for (int i = tid; i < HD*GW; i += THREADS) {
        int k = i / GW, w = i % GW;
        float gx    = ((float)w + 0.5f) * (1.0f / (float)GW);
        float rel_x = (gx - cx) * inv_bw;
        s_tx[k][w] = rel_x * s_w[2*k + 1];                   // w1x[k]
    }
    __syncthreads();

    // second-layer weights in registers
    float w2[HD];
    #pragma unroll
    for (int k = 0; k < HD; ++k) w2[k] = s_w[3*HD + k];
    const float b2 = s_w[4*HD];

    // ---- Phase 3: 576 quad-outputs, 3 per thread; float4 tx loads + float4 STG ----
    float* outp = out + (size_t)bq * (GH * GW);
    #pragma unroll
    for (int it = 0; it < NQUAD / THREADS; ++it) {
        int j  = tid + it * THREADS;     // 0..575
        int h  = j / (GW/4);
        int w  = (j % (GW/4)) * 4;

        float a0 = b2, a1 = b2, a2 = b2, a3 = b2;
        #pragma unroll
        for (int k = 0; k < HD; ++k) {
            float  tyv = s_ty[k][h];                                       // broadcast
            float4 txv = *reinterpret_cast<const float4*>(&s_tx[k][w]);    // stride-1 LDS.128
            float t0 = fmaxf(tyv + txv.x, 0.0f);
            float t1 = fmaxf(tyv + txv.y, 0.0f);
            float t2 = fmaxf(tyv + txv.z, 0.0f);
            float t3 = fmaxf(tyv + txv.w, 0.0f);
            a0 = fmaf(t0, w2[k], a0);
            a1 = fmaf(t1, w2[k], a1);
            a2 = fmaf(t2, w2[k], a2);
            a3 = fmaf(t3, w2[k], a3);
        }
        float4 r; r.x = a0; r.y = a1; r.z = a2; r.w = a3;
        *reinterpret_cast<float4*>(&outp[h * GW + w]) = r;   // coalesced STG.128
    }
}

extern "C" void kernel_launch(void* const* d_in, const int* in_sizes, int n_in,
                              void* d_out, int out_size)
{
    const float* queries = (const float*)d_in[0];
    const float* pos     = (const float*)d_in[1];
    const float* w_gen   = (const float*)d_in[2];
    const float* b_gen   = (const float*)d_in[3];
    float* out = (float*)d_out;

    int BQ = in_sizes[0] / C_DIM;   // B*Q = 1800
    posmlp_kernel<<<BQ, THREADS>>>(queries, pos, w_gen, b_gen, out);
}